// round 2
// baseline (speedup 1.0000x reference)
#include <cuda_runtime.h>

#define BB 8
#define NN 256
#define HH 128
#define EPSF 1e-20f

// Scratch (allocation-free rule: __device__ globals)
__device__ float g_Ux[BB * NN * HH];
__device__ float g_Vx[BB * NN * HH];

// ---------------------------------------------------------------------------
// Kernel 1: Ux = mask*(x@Uw^T + Ub), Vx = mask*(x@Vw^T + Vb)
// grid = (B*N)/R blocks, 128 threads. Thread t computes output feature o=t for
// R rows. x-tile staged in smem (broadcast reads), W streamed as float4 per
// thread (sequential -> L1-resident lines).
// ---------------------------------------------------------------------------
__global__ __launch_bounds__(128) void linear_kernel(
    const float* __restrict__ x, const float* __restrict__ mask,
    const float* __restrict__ Uw, const float* __restrict__ Ub,
    const float* __restrict__ Vw, const float* __restrict__ Vb)
{
    const int R = 8;
    __shared__ float xs[R][HH];
    const int row0 = blockIdx.x * R;
    const int t = threadIdx.x;  // o = t in [0,128)

    for (int idx = t; idx < R * HH; idx += 128)
        xs[idx / HH][idx % HH] = x[row0 * HH + idx];
    __syncthreads();

    float accU[R], accV[R];
#pragma unroll
    for (int r = 0; r < R; r++) { accU[r] = 0.f; accV[r] = 0.f; }

    const float4* Uw4 = reinterpret_cast<const float4*>(Uw + t * HH);
    const float4* Vw4 = reinterpret_cast<const float4*>(Vw + t * HH);

#pragma unroll 4
    for (int k4 = 0; k4 < HH / 4; k4++) {
        const float4 u = Uw4[k4];
        const float4 v = Vw4[k4];
#pragma unroll
        for (int r = 0; r < R; r++) {
            const float x0 = xs[r][k4 * 4 + 0];
            const float x1 = xs[r][k4 * 4 + 1];
            const float x2 = xs[r][k4 * 4 + 2];
            const float x3 = xs[r][k4 * 4 + 3];
            accU[r] = fmaf(x0, u.x, fmaf(x1, u.y, fmaf(x2, u.z, fmaf(x3, u.w, accU[r]))));
            accV[r] = fmaf(x0, v.x, fmaf(x1, v.y, fmaf(x2, v.z, fmaf(x3, v.w, accV[r]))));
        }
    }

    const float ub = Ub[t];
    const float vb = Vb[t];
#pragma unroll
    for (int r = 0; r < R; r++) {
        const int row = row0 + r;
        const float m = mask[row];
        g_Ux[row * HH + t] = m * (accU[r] + ub);
        g_Vx[row * HH + t] = m * (accV[r] + vb);
    }
}

// ---------------------------------------------------------------------------
// Kernel 2: out[b,i,h] = Ux + (mi * sum_j eg*mj*Vx[j]) / (EPS + mi * sum_j eg*mj)
// One block per (b,i). 128 threads = 4 warps; warp w covers j = w, w+4, ...
// Thread t: h4 = t&31 (float4 h-slice), jq = t>>5. Each warp load per j is a
// contiguous 512B segment -> perfect coalescing. __ldcs streams edge_gate
// (read-once, 256MB) past L2 so Vx/mask stay resident.
// ---------------------------------------------------------------------------
__global__ __launch_bounds__(128) void edge_kernel(
    const float* __restrict__ eg, const float* __restrict__ mask,
    float* __restrict__ out)
{
    const int bi = blockIdx.x;       // b*N + i
    const int b  = bi >> 8;          // N = 256
    const int t  = threadIdx.x;
    const int h4 = t & 31;
    const int jq = t >> 5;

    __shared__ float  msk[NN];
    __shared__ float4 sh0[4][32];
    __shared__ float4 sh1[4][32];

    for (int j = t; j < NN; j += 128) msk[j] = mask[b * NN + j];
    __syncthreads();

    const float4* egp = reinterpret_cast<const float4*>(eg + (size_t)bi * NN * HH) + h4;
    const float4* vxp = reinterpret_cast<const float4*>(g_Vx + (size_t)b * NN * HH) + h4;

    float4 s0 = make_float4(0.f, 0.f, 0.f, 0.f);
    float4 s1 = make_float4(0.f, 0.f, 0.f, 0.f);

#pragma unroll 4
    for (int j = jq; j < NN; j += 4) {
        float4 e = __ldcs(egp + (size_t)j * (HH / 4));
        const float4 v = __ldg(vxp + j * (HH / 4));
        const float mj = msk[j];
        e.x *= mj; e.y *= mj; e.z *= mj; e.w *= mj;
        s0.x += e.x; s0.y += e.y; s0.z += e.z; s0.w += e.w;
        s1.x = fmaf(e.x, v.x, s1.x);
        s1.y = fmaf(e.y, v.y, s1.y);
        s1.z = fmaf(e.z, v.z, s1.z);
        s1.w = fmaf(e.w, v.w, s1.w);
    }

    sh0[jq][h4] = s0;
    sh1[jq][h4] = s1;
    __syncthreads();

    if (t < 32) {
        float4 a0 = sh0[0][t];
        float4 a1 = sh1[0][t];
#pragma unroll
        for (int w = 1; w < 4; w++) {
            const float4 b0 = sh0[w][t];
            const float4 b1 = sh1[w][t];
            a0.x += b0.x; a0.y += b0.y; a0.z += b0.z; a0.w += b0.w;
            a1.x += b1.x; a1.y += b1.y; a1.z += b1.z; a1.w += b1.w;
        }
        const float mi = mask[bi];
        const float4 ux = reinterpret_cast<const float4*>(g_Ux)[(size_t)bi * (HH / 4) + t];
        float4 o;
        o.x = ux.x + (mi * a1.x) / (EPSF + mi * a0.x);
        o.y = ux.y + (mi * a1.y) / (EPSF + mi * a0.y);
        o.z = ux.z + (mi * a1.z) / (EPSF + mi * a0.z);
        o.w = ux.w + (mi * a1.w) / (EPSF + mi * a0.w);
        reinterpret_cast<float4*>(out)[(size_t)bi * (HH / 4) + t] = o;
    }
}

extern "C" void kernel_launch(void* const* d_in, const int* in_sizes, int n_in,
                              void* d_out, int out_size)
{
    const float* x   = (const float*)d_in[0];
    const float* eg  = (const float*)d_in[1];
    const float* msk = (const float*)d_in[2];
    const float* Uw  = (const float*)d_in[3];
    const float* Ub  = (const float*)d_in[4];
    const float* Vw  = (const float*)d_in[5];
    const float* Vb  = (const float*)d_in[6];
    float* out = (float*)d_out;

    linear_kernel<<<(BB * NN) / 8, 128>>>(x, msk, Uw, Ub, Vw, Vb);
    edge_kernel<<<BB * NN, 128>>>(eg, msk, out);
}

// round 3
// speedup vs baseline: 1.0634x; 1.0634x over previous
#include <cuda_runtime.h>

#define BB 8
#define NN 256
#define HH 128
#define EPSF 1e-20f

// Scratch (allocation-free rule: __device__ globals)
__device__ float g_Ux[BB * NN * HH];
__device__ float g_Vx[BB * NN * HH];

// ---------------------------------------------------------------------------
// Kernel 1: Ux = mask*(x@Uw^T + Ub), Vx = mask*(x@Vw^T + Vb)
// R=4 rows per block -> grid 512 (3.46 blocks/SM, small single-wave
// imbalance). Thread t = output feature o; weights streamed as float4
// (L1-resident across co-located blocks), x tile read as LDS.128 broadcast.
// ---------------------------------------------------------------------------
__global__ __launch_bounds__(128) void linear_kernel(
    const float* __restrict__ x, const float* __restrict__ mask,
    const float* __restrict__ Uw, const float* __restrict__ Ub,
    const float* __restrict__ Vw, const float* __restrict__ Vb)
{
    const int R = 4;
    __shared__ float4 xs[R][HH / 4];
    const int row0 = blockIdx.x * R;
    const int t = threadIdx.x;  // o in [0,128)

    // R*HH = 512 floats = 128 float4 -> one per thread
    reinterpret_cast<float4*>(xs)[t] =
        reinterpret_cast<const float4*>(x + (size_t)row0 * HH)[t];
    __syncthreads();

    float accU[R], accV[R];
#pragma unroll
    for (int r = 0; r < R; r++) { accU[r] = 0.f; accV[r] = 0.f; }

    const float4* Uw4 = reinterpret_cast<const float4*>(Uw + t * HH);
    const float4* Vw4 = reinterpret_cast<const float4*>(Vw + t * HH);

#pragma unroll 8
    for (int k4 = 0; k4 < HH / 4; k4++) {
        const float4 u = Uw4[k4];
        const float4 v = Vw4[k4];
#pragma unroll
        for (int r = 0; r < R; r++) {
            const float4 xr = xs[r][k4];  // broadcast LDS.128
            accU[r] = fmaf(xr.x, u.x, fmaf(xr.y, u.y, fmaf(xr.z, u.z, fmaf(xr.w, u.w, accU[r]))));
            accV[r] = fmaf(xr.x, v.x, fmaf(xr.y, v.y, fmaf(xr.z, v.z, fmaf(xr.w, v.w, accV[r]))));
        }
    }

    const float ub = Ub[t];
    const float vb = Vb[t];
#pragma unroll
    for (int r = 0; r < R; r++) {
        const int row = row0 + r;
        const float m = mask[row];
        g_Ux[(size_t)row * HH + t] = m * (accU[r] + ub);
        g_Vx[(size_t)row * HH + t] = m * (accV[r] + vb);
    }
}

// ---------------------------------------------------------------------------
// Kernel 2: out[b,i,h] = Ux + (mi*sum_j eg*mj*Vx[j]) / (EPS + mi*sum_j eg*mj)
// SINGLE WAVE: grid=512 blocks x 256 threads, each block owns exactly 4
// consecutive (b,i) tiles (same b -> mask loaded once). 512 <= 148*4 resident
// -> no straggler wave (R2's 62.7us at 55% DRAM was a 1628+420 two-wave tail).
// Warp layout: h4 = t&31 (float4 h-slice, 512B contiguous per warp-load),
// jq = t>>5 in [0,8). __ldcs streams the 256MB read-once edge_gate.
// ---------------------------------------------------------------------------
__global__ __launch_bounds__(256, 4) void edge_kernel(
    const float* __restrict__ eg, const float* __restrict__ mask,
    float* __restrict__ out)
{
    const int t  = threadIdx.x;
    const int h4 = t & 31;
    const int jq = t >> 5;               // 0..7
    const int bi0 = blockIdx.x * 4;
    const int b = bi0 >> 8;              // 4 | 256 -> same b for all 4 tiles

    __shared__ float  msk[NN];
    __shared__ float4 sh0[8][32];
    __shared__ float4 sh1[8][32];

    msk[t] = mask[b * NN + t];           // 256 threads, NN=256
    __syncthreads();

    const float4* vxp = reinterpret_cast<const float4*>(g_Vx + (size_t)b * NN * HH) + h4;

#pragma unroll 1
    for (int q = 0; q < 4; q++) {
        const int bi = bi0 + q;
        const float4* egp = reinterpret_cast<const float4*>(eg + (size_t)bi * NN * HH) + h4;

        float4 s0 = make_float4(0.f, 0.f, 0.f, 0.f);
        float4 s1 = make_float4(0.f, 0.f, 0.f, 0.f);

#pragma unroll 4
        for (int j = jq; j < NN; j += 8) {
            float4 e = __ldcs(egp + (size_t)j * (HH / 4));
            const float4 v = __ldg(vxp + j * (HH / 4));
            const float mj = msk[j];
            e.x *= mj; e.y *= mj; e.z *= mj; e.w *= mj;
            s0.x += e.x; s0.y += e.y; s0.z += e.z; s0.w += e.w;
            s1.x = fmaf(e.x, v.x, s1.x);
            s1.y = fmaf(e.y, v.y, s1.y);
            s1.z = fmaf(e.z, v.z, s1.z);
            s1.w = fmaf(e.w, v.w, s1.w);
        }

        sh0[jq][h4] = s0;
        sh1[jq][h4] = s1;
        __syncthreads();

        if (t < 32) {
            float4 a0 = sh0[0][t];
            float4 a1 = sh1[0][t];
#pragma unroll
            for (int w = 1; w < 8; w++) {
                const float4 b0 = sh0[w][t];
                const float4 b1 = sh1[w][t];
                a0.x += b0.x; a0.y += b0.y; a0.z += b0.z; a0.w += b0.w;
                a1.x += b1.x; a1.y += b1.y; a1.z += b1.z; a1.w += b1.w;
            }
            const float mi = mask[bi];
            const float4 ux = reinterpret_cast<const float4*>(g_Ux)[(size_t)bi * (HH / 4) + t];
            float4 o;
            o.x = ux.x + (mi * a1.x) / (EPSF + mi * a0.x);
            o.y = ux.y + (mi * a1.y) / (EPSF + mi * a0.y);
            o.z = ux.z + (mi * a1.z) / (EPSF + mi * a0.z);
            o.w = ux.w + (mi * a1.w) / (EPSF + mi * a0.w);
            reinterpret_cast<float4*>(out)[(size_t)bi * (HH / 4) + t] = o;
        }
        __syncthreads();  // smem reuse across q
    }
}

extern "C" void kernel_launch(void* const* d_in, const int* in_sizes, int n_in,
                              void* d_out, int out_size)
{
    const float* x   = (const float*)d_in[0];
    const float* eg  = (const float*)d_in[1];
    const float* msk = (const float*)d_in[2];
    const float* Uw  = (const float*)d_in[3];
    const float* Ub  = (const float*)d_in[4];
    const float* Vw  = (const float*)d_in[5];
    const float* Vb  = (const float*)d_in[6];
    float* out = (float*)d_out;

    linear_kernel<<<(BB * NN) / 4, 128>>>(x, msk, Uw, Ub, Vw, Vb);
    edge_kernel<<<(BB * NN) / 4, 256>>>(eg, msk, out);
}